// round 11
// baseline (speedup 1.0000x reference)
#include <cuda_runtime.h>
#include <cstdint>

#define BB 64
#define SS 512
#define HH 768
#define KK 21
#define FULLMASK 0xffffffffu
#define LOG21 3.0445224377234229f

// ---------------------------------------------------------------------------
// helpers
// ---------------------------------------------------------------------------
__device__ __forceinline__ void fma2(unsigned long long& acc,
                                     unsigned long long a,
                                     unsigned long long b) {
    asm("fma.rn.f32x2 %0, %1, %2, %0;" : "+l"(acc) : "l"(a), "l"(b));
}
__device__ __forceinline__ float2 unpack2(unsigned long long v) {
    float lo, hi;
    asm("mov.b64 {%0,%1}, %2;" : "=f"(lo), "=f"(hi) : "l"(v));
    return make_float2(lo, hi);
}
__device__ __forceinline__ float rcpa(float x) {
    float r;
    asm("rcp.approx.f32 %0, %1;" : "=f"(r) : "f"(x));
    return r;
}
__device__ __forceinline__ void cpa8(void* dst, const void* src) {
    uint32_t d = (uint32_t)__cvta_generic_to_shared(dst);
    asm volatile("cp.async.ca.shared.global [%0], [%1], 8;\n" ::"r"(d), "l"(src));
}
__device__ __forceinline__ void cpa16(void* dst, const void* src) {
    uint32_t d = (uint32_t)__cvta_generic_to_shared(dst);
    asm volatile("cp.async.cg.shared.global [%0], [%1], 16;\n" ::"r"(d), "l"(src));
}

__device__ float4 g_wpack[384 * 11];
__device__ float  g_partial[BB];
__device__ int    g_ctr = 0;
__device__ int    g_packflag = 0;

__device__ __forceinline__ void wait_flag(volatile int* f) {
    while (*f == 0) __nanosleep(64);
}

// CRF scan scratch
__device__ float g_a1v[BB][32];
__device__ float g_cfv[BB];
__device__ float g_dv[BB][32];
__device__ float g_cdv[BB];
__device__ float g_numv[BB];
__device__ float g_colsv[BB][2][KK][32];
__device__ float g_lcv[BB][2][KK];
__device__ int   g_seqctr[BB];   // zero-init

// ---------------------------------------------------------------------------
// GEMM (identical to R9/R10): 512 tiles of 64 rows; block 0 packs W.
// ---------------------------------------------------------------------------
#define GT    128
#define GR    64
#define GSTR  66
#define WCH   352
#define NCH   12
#define HFLOATS (GR * GSTR)
#define GSMEM (2 * HFLOATS * 4 + 2 * WCH * 16)

__global__ __launch_bounds__(GT) void gemm_kernel(
    const float* __restrict__ hidden,
    const float* __restrict__ Wg,
    const float* __restrict__ bg,
    float* __restrict__ out) {
    extern __shared__ float dsm[];
    const int tid = threadIdx.x;

    if (blockIdx.x == 0) {
        for (int idx = tid; idx < 384 * 11; idx += GT) {
            int p = idx / 11, cc = idx - p * 11;
            int c0 = 2 * cc, c1 = c0 + 1;
            float a = Wg[(2 * p)     * KK + c0];
            float b = Wg[(2 * p + 1) * KK + c0];
            float c = (c1 < KK) ? Wg[(2 * p)     * KK + c1] : 0.f;
            float d = (c1 < KK) ? Wg[(2 * p + 1) * KK + c1] : 0.f;
            g_wpack[idx] = make_float4(a, b, c, d);
        }
        __threadfence();
        __syncthreads();
        if (tid == 0) atomicExch(&g_packflag, 1);
        return;
    }

    float*  shh = dsm;
    float4* wb  = (float4*)(dsm + 2 * HFLOATS);
    const int r = tid & 31;
    const int q = tid >> 5;
    const size_t rowBase = (size_t)(blockIdx.x - 1) * GR;

    auto LOADH = [&](int c, int buf) {
        const float* hsrc = hidden + rowBase * HH + c * 64;
        float* dst = shh + buf * HFLOATS;
#pragma unroll
        for (int j = 0; j < 16; j++) {
            int idx = tid + j * GT;
            int row = idx >> 5, u8 = idx & 31;
            cpa8(&dst[row * GSTR + u8 * 2], hsrc + (size_t)row * HH + u8 * 2);
        }
    };
    auto LOADW = [&](int c, int buf) {
#pragma unroll
        for (int j = 0; j < 3; j++) {
            int idx = tid + j * GT;
            if (idx < WCH) cpa16(&wb[buf * WCH + idx], &g_wpack[c * WCH + idx]);
        }
    };

    unsigned long long accA[KK], accB[KK];
#pragma unroll
    for (int i = 0; i < KK; i++) { accA[i] = 0ull; accB[i] = 0ull; }

    LOADH(0, 0);
    asm volatile("cp.async.commit_group;\n");
    wait_flag(&g_packflag);
    __threadfence();
    LOADW(0, 0);
    asm volatile("cp.async.commit_group;\n");

    for (int c = 0; c < NCH; c++) {
        if (c + 1 < NCH) {
            LOADH(c + 1, (c + 1) & 1);
            LOADW(c + 1, (c + 1) & 1);
            asm volatile("cp.async.commit_group;\n");
            asm volatile("cp.async.wait_group 1;\n");
        } else {
            asm volatile("cp.async.wait_group 0;\n");
        }
        __syncthreads();

        const float*  hpA = &shh[(c & 1) * HFLOATS + r * GSTR + q * 16];
        const float*  hpB = hpA + 32 * GSTR;
        const float4* wp  = &wb[(c & 1) * WCH + (q * 8) * 11];
#pragma unroll
        for (int p = 0; p < 8; p++) {
            unsigned long long h2a = *(const unsigned long long*)&hpA[2 * p];
            unsigned long long h2b = *(const unsigned long long*)&hpB[2 * p];
            const ulonglong2* wrow = (const ulonglong2*)&wp[p * 11];
#pragma unroll
            for (int cc = 0; cc < 10; cc++) {
                ulonglong2 w2 = wrow[cc];
                fma2(accA[2 * cc],     h2a, w2.x);
                fma2(accA[2 * cc + 1], h2a, w2.y);
                fma2(accB[2 * cc],     h2b, w2.x);
                fma2(accB[2 * cc + 1], h2b, w2.y);
            }
            ulonglong2 w2 = wrow[10];
            fma2(accA[20], h2a, w2.x);
            fma2(accB[20], h2b, w2.x);
        }
        __syncthreads();
    }

    float resA[KK], resB[KK];
#pragma unroll
    for (int cc = 0; cc < KK; cc++) {
        float2 fa = unpack2(accA[cc]);
        float2 fb = unpack2(accB[cc]);
        resA[cc] = fa.x + fa.y;
        resB[cc] = fb.x + fb.y;
    }
    float* bufA  = shh;
    float* bufB  = shh + GR * 22;
    float* shOut = shh + 2 * GR * 22;
    if (q == 1 || q == 3) {
        float* bf = (q == 1) ? bufA : bufB;
#pragma unroll
        for (int cc = 0; cc < KK; cc++) {
            bf[r * 22 + cc] = resA[cc];
            bf[(32 + r) * 22 + cc] = resB[cc];
        }
    }
    __syncthreads();
    if (q == 0 || q == 2) {
        float* bf = (q == 0) ? bufA : bufB;
#pragma unroll
        for (int cc = 0; cc < KK; cc++) {
            resA[cc] += bf[r * 22 + cc];
            resB[cc] += bf[(32 + r) * 22 + cc];
        }
    }
    __syncthreads();
    if (q == 2) {
#pragma unroll
        for (int cc = 0; cc < KK; cc++) {
            bufA[r * 22 + cc] = resA[cc];
            bufA[(32 + r) * 22 + cc] = resB[cc];
        }
    }
    __syncthreads();
    if (q == 0) {
#pragma unroll
        for (int cc = 0; cc < KK; cc++) {
            shOut[r * KK + cc] = resA[cc] + bufA[r * 22 + cc] + bg[cc];
            shOut[(32 + r) * KK + cc] =
                resB[cc] + bufA[(32 + r) * 22 + cc] + bg[cc];
        }
    }
    __syncthreads();
    float* outp = out + rowBase * KK;
    for (int i = tid; i < GR * KK; i += GT) outp[i] = shOut[i];
}

// ---------------------------------------------------------------------------
// CRF scan: smem-broadcast step, RN=8 renorm (folded), 4 segments.
// ---------------------------------------------------------------------------
#define RN 8

__device__ __forceinline__ int seq_len_w(const void* maskraw, int b, int lane) {
    const int* im = (const int*)maskraw;
    bool bytes = (im[0] != 1);
    int len = 0;
    if (!bytes) {
        const int* m = im + b * SS;
        for (int t = lane; t < SS; t += 32) len += (m[t] != 0);
    } else {
        const unsigned char* m = (const unsigned char*)maskraw + b * SS;
        for (int t = lane; t < SS; t += 32) len += (m[t] != 0);
    }
#pragma unroll
    for (int o = 16; o; o >>= 1) len += __shfl_xor_sync(FULLMASK, len, o);
    return len;
}

__device__ __forceinline__ float crf_sstep(float* sb, int rb, const float* tE,
                                           float e0, int lane) {
    const float4* sp = (const float4*)(sb + rb * 24);
    float4 v0 = sp[0], v1 = sp[1], v2 = sp[2], v3 = sp[3], v4 = sp[4], v5 = sp[5];
    float a0 = v0.x * tE[0];
    a0 = fmaf(v0.y, tE[1], a0); a0 = fmaf(v0.z, tE[2], a0); a0 = fmaf(v0.w, tE[3], a0);
    float a1 = v1.x * tE[4];
    a1 = fmaf(v1.y, tE[5], a1); a1 = fmaf(v1.z, tE[6], a1); a1 = fmaf(v1.w, tE[7], a1);
    float a2 = v2.x * tE[8];
    a2 = fmaf(v2.y, tE[9], a2); a2 = fmaf(v2.z, tE[10], a2); a2 = fmaf(v2.w, tE[11], a2);
    float a3 = v3.x * tE[12];
    a3 = fmaf(v3.y, tE[13], a3); a3 = fmaf(v3.z, tE[14], a3); a3 = fmaf(v3.w, tE[15], a3);
    float a4 = v4.x * tE[16];
    a4 = fmaf(v4.y, tE[17], a4); a4 = fmaf(v4.z, tE[18], a4); a4 = fmaf(v4.w, tE[19], a4);
    float a5 = v5.x * tE[20];
    float y = ((a0 + a1) + (a2 + a3)) + (a4 + a5);
    float u = y * e0;
    if (lane < KK) sb[(rb ^ 1) * 24 + lane] = u;
    __syncwarp();
    return u;
}

__device__ __forceinline__ float crf_run_s(float uinit, float& logC,
                                           const float* tE, float* sb,
                                           const float* lg, int jj,
                                           int base, int dir, int n, int lane) {
    if (lane < 24) {
        sb[lane]      = (lane < KK) ? uinit : 0.f;
        sb[24 + lane] = 0.f;
    }
    __syncwarp();
    if (n <= 0) return uinit;

    float u = uinit;
    float ev[RN], evn[RN];
#pragma unroll
    for (int j = 0; j < RN; j++) {
        int idx = (j < n) ? j : n - 1;
        ev[j] = lg[(base + dir * idx) * KK + jj];
    }
    float pend = 1.f, lpend = 0.f;
    int rb = 0;
    int pos = 0;
    while (pos + RN <= n) {
#pragma unroll
        for (int j = 0; j < RN; j++) {
            int idx = pos + RN + j; idx = (idx < n) ? idx : n - 1;
            evn[j] = lg[(base + dir * idx) * KK + jj];
        }
        float e0 = __expf(ev[0]) * pend;
        logC += lpend;
#pragma unroll
        for (int j = 0; j < RN; j++) {
            float e1 = __expf(ev[(j + 1) & (RN - 1)]);
            u = crf_sstep(sb, rb, tE, e0, lane);
            rb ^= 1;
            e0 = e1;
        }
        float c = sb[rb * 24];
        pend = rcpa(c);
        lpend = __logf(c);
#pragma unroll
        for (int j = 0; j < RN; j++) ev[j] = evn[j];
        pos += RN;
    }
    int tail = n - pos;
    if (tail) {
        float e0 = __expf(ev[0]) * pend;
        logC += lpend;
        for (int j = 0; j < tail; j++) {
            u = crf_sstep(sb, rb, tE, e0, lane);
            rb ^= 1;
            e0 = __expf(ev[(j + 1) & (RN - 1)]);
        }
    }
    logC += (float)n * LOG21;
    return u;
}

// ---------------------------------------------------------------------------
// crf_scan: grid (BB, 4), 384 threads (12 warps). Task map (role*12+warp):
//   0: fwd vec      1: numerator   2-11:  M1 cols 0-9
//   12: bwd vec     13-23:         M1 cols 10-20
//   24-34: M2 cols 0-10            35-44: M2 cols 11-20
// ---------------------------------------------------------------------------
__global__ __launch_bounds__(384, 2) void crf_scan(
    const float* __restrict__ logits,
    const int*   __restrict__ labels,
    const void*  __restrict__ maskraw,
    const float* __restrict__ start_t,
    const float* __restrict__ trans,
    const float* __restrict__ end_t,
    float* __restrict__ out_nll) {
    const int b = blockIdx.x;
    const int role = blockIdx.y;
    const int tid = threadIdx.x;
    const int w = tid >> 5;
    const int lane = tid & 31;
    const int jj = (lane < KK) ? lane : KK - 1;
    const int task = role * 12 + w;

    __shared__ __align__(16) float s_st[12][48];

    const int len = seq_len_w(maskraw, b, lane);
    const int q1 = len >> 2, q2 = len >> 1, q3 = (3 * len) >> 2;
    const float* lg  = logits + (size_t)b * SS * KK;
    const int*   lab = labels + b * SS;

    if (task == 0) {
        // forward vector: alpha_0 -> alpha_q1
        float tE[24];
#pragma unroll
        for (int i = 0; i < KK; i++)
            tE[i] = __expf(trans[i * KK + jj]) * (1.f / 21.f);
        tE[21] = tE[22] = tE[23] = 0.f;
        float a0 = (lane < KK) ? (start_t[lane] + lg[lane]) : -1e30f;
        float m0 = a0;
#pragma unroll
        for (int o = 16; o; o >>= 1)
            m0 = fmaxf(m0, __shfl_xor_sync(FULLMASK, m0, o));
        float u = __expf(a0 - m0);
        float logC = m0;
        u = crf_run_s(u, logC, tE, s_st[w], lg, jj, 1, +1, q1, lane);
        g_a1v[b][lane] = (lane < KK) ? u : 0.f;
        if (lane == 0) g_cfv[b] = logC;
    } else if (task == 1) {
        // numerator
        float num = 0.f;
        for (int t = lane; t < len; t += 32) {
            int lt = lab[t];
            float e = lg[t * KK + lt];
            num += (t == 0) ? (start_t[lt] + e)
                            : (e + trans[lab[t - 1] * KK + lt]);
        }
#pragma unroll
        for (int o = 16; o; o >>= 1) num += __shfl_xor_sync(FULLMASK, num, o);
        if (lane == 0) g_numv[b] = num + end_t[lab[len - 1]];
    } else if (task == 12) {
        // backward vector: beta_{len-1} -> beta_q3
        float tEb[24];
#pragma unroll
        for (int i = 0; i < KK; i++)
            tEb[i] = __expf(trans[jj * KK + i]) * (1.f / 21.f);
        tEb[21] = tEb[22] = tEb[23] = 0.f;
        float v = __expf(end_t[jj]);
        float logC = 0.f;
        v = crf_run_s(v, logC, tEb, s_st[w], lg, jj, len - 1, -1,
                      len - 1 - q3, lane);
        g_dv[b][lane] = (lane < KK) ? v : 0.f;
        if (lane == 0) g_cdv[b] = logC;
    } else if (task < 45 && task != 1) {
        // matrix column tasks
        int seg, col;
        if (task >= 2 && task <= 11)       { seg = 0; col = task - 2; }
        else if (task >= 13 && task <= 23) { seg = 0; col = task - 3; }
        else if (task >= 24 && task <= 34) { seg = 1; col = task - 24; }
        else                               { seg = 1; col = task - 24; } // 35-44 -> 11-20
        float tE[24];
#pragma unroll
        for (int i = 0; i < KK; i++)
            tE[i] = __expf(trans[i * KK + jj]) * (1.f / 21.f);
        tE[21] = tE[22] = tE[23] = 0.f;
        float u0 = (lane == col) ? 1.f : 0.f;
        float logC = 0.f;
        int base = (seg == 0) ? (q1 + 1) : (q2 + 1);
        int n    = (seg == 0) ? (q2 - q1) : (q3 - q2);
        float u = crf_run_s(u0, logC, tE, s_st[w], lg, jj, base, +1, n, lane);
        g_colsv[b][seg][col][lane] = (lane < KK) ? u : 0.f;
        if (lane == 0) g_lcv[b][seg][col] = logC;
    }

    __syncthreads();
    __shared__ int sOld;
    if (tid == 0) {
        __threadfence();
        sOld = atomicAdd(&g_seqctr[b], 1);
    }
    __syncthreads();
    if (sOld != 3 || w != 0) return;

    // -------- combine (warp 0 of last-arriving block) --------
    __threadfence();
    float a = g_a1v[b][lane];
    float cacc = g_cfv[b];
#pragma unroll
    for (int seg = 0; seg < 2; seg++) {
        float lc = (lane < KK) ? g_lcv[b][seg][lane] : -1e30f;
        float ref = lc;
#pragma unroll
        for (int o = 16; o; o >>= 1)
            ref = fmaxf(ref, __shfl_xor_sync(FULLMASK, ref, o));
        float sj = (lane < KK) ? a * __expf(lc - ref) : 0.f;
        float anew = 0.f;
#pragma unroll
        for (int j = 0; j < KK; j++) {
            float sjj = __shfl_sync(FULLMASK, sj, j);
            anew = fmaf(sjj, g_colsv[b][seg][j][lane], anew);
        }
        if (seg == 0) {
            float c0 = __shfl_sync(FULLMASK, anew, 0);
            anew = anew / c0;
            cacc += ref + logf(c0);
        } else {
            cacc += ref;
        }
        a = anew;
    }
    float z = (lane < KK) ? a * g_dv[b][lane] : 0.f;
#pragma unroll
    for (int o = 16; o; o >>= 1) z += __shfl_xor_sync(FULLMASK, z, o);
    float logZ = logf(z) + cacc + g_cdv[b];

    if (lane == 0) {
        g_partial[b] = logZ - g_numv[b];
        g_seqctr[b] = 0;
        __threadfence();
        int old = atomicAdd(&g_ctr, 1);
        if (old == BB - 1) {
            __threadfence();
            float tot = 0.f;
            for (int i = 0; i < BB; i++) tot += g_partial[i];
            out_nll[0] = tot;
            g_ctr = 0;
        }
    }
}

// ---------------------------------------------------------------------------
extern "C" void kernel_launch(void* const* d_in, const int* in_sizes, int n_in,
                              void* d_out, int out_size) {
    const float* hidden  = (const float*)d_in[0];
    const float* W       = (const float*)d_in[1];
    const float* b       = (const float*)d_in[2];
    const float* start_t = (const float*)d_in[3];
    const float* trans   = (const float*)d_in[4];
    const float* end_t   = (const float*)d_in[5];
    const int*   labels  = (const int*)d_in[6];
    const void*  mask    = (const void*)d_in[7];

    float* out     = (float*)d_out;
    float* out_nll = out + (out_size - 1);

    cudaFuncSetAttribute(gemm_kernel,
                         cudaFuncAttributeMaxDynamicSharedMemorySize, GSMEM);

    gemm_kernel<<<1 + (BB * SS) / GR, GT, GSMEM>>>(hidden, W, b, out);
    crf_scan<<<dim3(BB, 4), 384>>>(out, labels, mask, start_t, trans, end_t,
                                   out_nll);
}

// round 12
// speedup vs baseline: 1.1693x; 1.1693x over previous
#include <cuda_runtime.h>
#include <cstdint>

#define BB 64
#define SS 512
#define HH 768
#define KK 21
#define FULLMASK 0xffffffffu
#define LOG21 3.0445224377234229f

typedef unsigned long long ull;

// ---------------------------------------------------------------------------
// helpers
// ---------------------------------------------------------------------------
__device__ __forceinline__ void fma2(ull& acc, ull a, ull b) {
    asm("fma.rn.f32x2 %0, %1, %2, %0;" : "+l"(acc) : "l"(a), "l"(b));
}
__device__ __forceinline__ ull add2(ull a, ull b) {
    ull r;
    asm("add.rn.f32x2 %0, %1, %2;" : "=l"(r) : "l"(a), "l"(b));
    return r;
}
__device__ __forceinline__ ull packf2(float lo, float hi) {
    ull r;
    asm("mov.b64 %0, {%1, %2};" : "=l"(r) : "f"(lo), "f"(hi));
    return r;
}
__device__ __forceinline__ float2 unpack2(ull v) {
    float lo, hi;
    asm("mov.b64 {%0,%1}, %2;" : "=f"(lo), "=f"(hi) : "l"(v));
    return make_float2(lo, hi);
}
__device__ __forceinline__ float rcpa(float x) {
    float r;
    asm("rcp.approx.f32 %0, %1;" : "=f"(r) : "f"(x));
    return r;
}
__device__ __forceinline__ void cpa8(void* dst, const void* src) {
    uint32_t d = (uint32_t)__cvta_generic_to_shared(dst);
    asm volatile("cp.async.ca.shared.global [%0], [%1], 8;\n" ::"r"(d), "l"(src));
}
__device__ __forceinline__ void cpa16(void* dst, const void* src) {
    uint32_t d = (uint32_t)__cvta_generic_to_shared(dst);
    asm volatile("cp.async.cg.shared.global [%0], [%1], 16;\n" ::"r"(d), "l"(src));
}

__device__ float4 g_wpack[384 * 11];
__device__ float  g_partial[BB];
__device__ int    g_ctr = 0;
__device__ int    g_packflag = 0;

__device__ __forceinline__ void wait_flag(volatile int* f) {
    while (*f == 0) __nanosleep(64);
}

// ---------------------------------------------------------------------------
// GEMM (identical to R9/R10): 512 tiles of 64 rows; block 0 packs W.
// ---------------------------------------------------------------------------
#define GT    128
#define GR    64
#define GSTR  66
#define WCH   352
#define NCH   12
#define HFLOATS (GR * GSTR)
#define GSMEM (2 * HFLOATS * 4 + 2 * WCH * 16)

__global__ __launch_bounds__(GT) void gemm_kernel(
    const float* __restrict__ hidden,
    const float* __restrict__ Wg,
    const float* __restrict__ bg,
    float* __restrict__ out) {
    extern __shared__ float dsm[];
    const int tid = threadIdx.x;

    if (blockIdx.x == 0) {
        for (int idx = tid; idx < 384 * 11; idx += GT) {
            int p = idx / 11, cc = idx - p * 11;
            int c0 = 2 * cc, c1 = c0 + 1;
            float a = Wg[(2 * p)     * KK + c0];
            float b = Wg[(2 * p + 1) * KK + c0];
            float c = (c1 < KK) ? Wg[(2 * p)     * KK + c1] : 0.f;
            float d = (c1 < KK) ? Wg[(2 * p + 1) * KK + c1] : 0.f;
            g_wpack[idx] = make_float4(a, b, c, d);
        }
        __threadfence();
        __syncthreads();
        if (tid == 0) atomicExch(&g_packflag, 1);
        return;
    }

    float*  shh = dsm;
    float4* wb  = (float4*)(dsm + 2 * HFLOATS);
    const int r = tid & 31;
    const int q = tid >> 5;
    const size_t rowBase = (size_t)(blockIdx.x - 1) * GR;

    auto LOADH = [&](int c, int buf) {
        const float* hsrc = hidden + rowBase * HH + c * 64;
        float* dst = shh + buf * HFLOATS;
#pragma unroll
        for (int j = 0; j < 16; j++) {
            int idx = tid + j * GT;
            int row = idx >> 5, u8 = idx & 31;
            cpa8(&dst[row * GSTR + u8 * 2], hsrc + (size_t)row * HH + u8 * 2);
        }
    };
    auto LOADW = [&](int c, int buf) {
#pragma unroll
        for (int j = 0; j < 3; j++) {
            int idx = tid + j * GT;
            if (idx < WCH) cpa16(&wb[buf * WCH + idx], &g_wpack[c * WCH + idx]);
        }
    };

    ull accA[KK], accB[KK];
#pragma unroll
    for (int i = 0; i < KK; i++) { accA[i] = 0ull; accB[i] = 0ull; }

    LOADH(0, 0);
    asm volatile("cp.async.commit_group;\n");
    wait_flag(&g_packflag);
    __threadfence();
    LOADW(0, 0);
    asm volatile("cp.async.commit_group;\n");

    for (int c = 0; c < NCH; c++) {
        if (c + 1 < NCH) {
            LOADH(c + 1, (c + 1) & 1);
            LOADW(c + 1, (c + 1) & 1);
            asm volatile("cp.async.commit_group;\n");
            asm volatile("cp.async.wait_group 1;\n");
        } else {
            asm volatile("cp.async.wait_group 0;\n");
        }
        __syncthreads();

        const float*  hpA = &shh[(c & 1) * HFLOATS + r * GSTR + q * 16];
        const float*  hpB = hpA + 32 * GSTR;
        const float4* wp  = &wb[(c & 1) * WCH + (q * 8) * 11];
#pragma unroll
        for (int p = 0; p < 8; p++) {
            ull h2a = *(const ull*)&hpA[2 * p];
            ull h2b = *(const ull*)&hpB[2 * p];
            const ulonglong2* wrow = (const ulonglong2*)&wp[p * 11];
#pragma unroll
            for (int cc = 0; cc < 10; cc++) {
                ulonglong2 w2 = wrow[cc];
                fma2(accA[2 * cc],     h2a, w2.x);
                fma2(accA[2 * cc + 1], h2a, w2.y);
                fma2(accB[2 * cc],     h2b, w2.x);
                fma2(accB[2 * cc + 1], h2b, w2.y);
            }
            ulonglong2 w2 = wrow[10];
            fma2(accA[20], h2a, w2.x);
            fma2(accB[20], h2b, w2.x);
        }
        __syncthreads();
    }

    float resA[KK], resB[KK];
#pragma unroll
    for (int cc = 0; cc < KK; cc++) {
        float2 fa = unpack2(accA[cc]);
        float2 fb = unpack2(accB[cc]);
        resA[cc] = fa.x + fa.y;
        resB[cc] = fb.x + fb.y;
    }
    float* bufA  = shh;
    float* bufB  = shh + GR * 22;
    float* shOut = shh + 2 * GR * 22;
    if (q == 1 || q == 3) {
        float* bf = (q == 1) ? bufA : bufB;
#pragma unroll
        for (int cc = 0; cc < KK; cc++) {
            bf[r * 22 + cc] = resA[cc];
            bf[(32 + r) * 22 + cc] = resB[cc];
        }
    }
    __syncthreads();
    if (q == 0 || q == 2) {
        float* bf = (q == 0) ? bufA : bufB;
#pragma unroll
        for (int cc = 0; cc < KK; cc++) {
            resA[cc] += bf[r * 22 + cc];
            resB[cc] += bf[(32 + r) * 22 + cc];
        }
    }
    __syncthreads();
    if (q == 2) {
#pragma unroll
        for (int cc = 0; cc < KK; cc++) {
            bufA[r * 22 + cc] = resA[cc];
            bufA[(32 + r) * 22 + cc] = resB[cc];
        }
    }
    __syncthreads();
    if (q == 0) {
#pragma unroll
        for (int cc = 0; cc < KK; cc++) {
            shOut[r * KK + cc] = resA[cc] + bufA[r * 22 + cc] + bg[cc];
            shOut[(32 + r) * KK + cc] =
                resB[cc] + bufA[(32 + r) * 22 + cc] + bg[cc];
        }
    }
    __syncthreads();
    float* outp = out + rowBase * KK;
    for (int i = tid; i < GR * KK; i += GT) outp[i] = shOut[i];
}

// ---------------------------------------------------------------------------
// CRF: bidirectional, state in warp-private smem double buffer.
//   Step: 6x LDS.128 (read as f32x2 pairs) + 12 fma2 + 1 STS + syncwarp.
// ---------------------------------------------------------------------------
#define RN 16

__device__ __forceinline__ int seq_len_w(const void* maskraw, int b, int lane) {
    const int* im = (const int*)maskraw;
    bool bytes = (im[0] != 1);
    int len = 0;
    if (!bytes) {
        const int* m = im + b * SS;
        for (int t = lane; t < SS; t += 32) len += (m[t] != 0);
    } else {
        const unsigned char* m = (const unsigned char*)maskraw + b * SS;
        for (int t = lane; t < SS; t += 32) len += (m[t] != 0);
    }
#pragma unroll
    for (int o = 16; o; o >>= 1) len += __shfl_xor_sync(FULLMASK, len, o);
    return len;
}

// one step with packed-pair dot
__device__ __forceinline__ float crf_sstep(float* sb, int rb, const ull* tE2,
                                           float e0, int lane) {
    const ulonglong2* sp = (const ulonglong2*)(sb + rb * 24);
    ulonglong2 q0 = sp[0], q1 = sp[1], q2 = sp[2];
    ulonglong2 q3 = sp[3], q4 = sp[4], q5 = sp[5];
    ull A = 0ull, B = 0ull, C = 0ull;
    fma2(A, q0.x, tE2[0]);  fma2(B, q0.y, tE2[1]);  fma2(C, q1.x, tE2[2]);
    fma2(A, q1.y, tE2[3]);  fma2(B, q2.x, tE2[4]);  fma2(C, q2.y, tE2[5]);
    fma2(A, q3.x, tE2[6]);  fma2(B, q3.y, tE2[7]);  fma2(C, q4.x, tE2[8]);
    fma2(A, q4.y, tE2[9]);  fma2(B, q5.x, tE2[10]); fma2(C, q5.y, tE2[11]);
    A = add2(A, B);
    A = add2(A, C);
    float2 f = unpack2(A);
    float u = (f.x + f.y) * e0;
    if (lane < KK) sb[(rb ^ 1) * 24 + lane] = u;
    __syncwarp();
    return u;
}

// n steps; emission t-index = base + dir*stepIdx. sb = warp-private [2][24].
__device__ __forceinline__ float crf_run_s(float uinit, float& logC,
                                           const ull* tE2, float* sb,
                                           const float* lg, int jj,
                                           int base, int dir, int n, int lane) {
    if (lane < 24) {
        sb[lane]      = (lane < KK) ? uinit : 0.f;
        sb[24 + lane] = 0.f;
    }
    __syncwarp();
    if (n <= 0) return uinit;

    float u = uinit;
    float ev[RN], evn[RN];
#pragma unroll
    for (int j = 0; j < RN; j++) {
        int idx = (j < n) ? j : n - 1;
        ev[j] = lg[(base + dir * idx) * KK + jj];
    }
    float pend = 1.f, lpend = 0.f;
    int rb = 0;
    int pos = 0;
    while (pos + RN <= n) {
#pragma unroll
        for (int j = 0; j < RN; j++) {
            int idx = pos + RN + j; idx = (idx < n) ? idx : n - 1;
            evn[j] = lg[(base + dir * idx) * KK + jj];
        }
        float e0 = __expf(ev[0]) * pend;
        logC += lpend;
#pragma unroll
        for (int j = 0; j < RN; j++) {
            float e1 = __expf(ev[(j + 1) & (RN - 1)]);
            u = crf_sstep(sb, rb, tE2, e0, lane);
            rb ^= 1;
            e0 = e1;
        }
        float c = sb[rb * 24];
        pend = rcpa(c);
        lpend = __logf(c);
#pragma unroll
        for (int j = 0; j < RN; j++) ev[j] = evn[j];
        pos += RN;
    }
    int tail = n - pos;
    if (tail) {
        float e0 = __expf(ev[0]) * pend;
        logC += lpend;
        for (int j = 0; j < tail; j++) {
            u = crf_sstep(sb, rb, tE2, e0, lane);
            rb ^= 1;
            e0 = __expf(ev[(j + 1) & (RN - 1)]);
        }
    }
    logC += (float)n * LOG21;
    return u;
}

__global__ __launch_bounds__(96) void crf_kernel(
    const float* __restrict__ logits,
    const int*   __restrict__ labels,
    const void*  __restrict__ maskraw,
    const float* __restrict__ start_t,
    const float* __restrict__ trans,
    const float* __restrict__ end_t,
    float* __restrict__ out_nll) {
    const int b = blockIdx.x;
    const int tid = threadIdx.x;
    const int lane = tid & 31;
    const int w = tid >> 5;
    const int jj = (lane < KK) ? lane : KK - 1;

    __shared__ __align__(16) float s_st[2][2 * 24];
    __shared__ float s_uf[32], s_ub[32];
    __shared__ float s_cf, s_cb, s_num, s_end;

    const int len = seq_len_w(maskraw, b, lane);
    const int m = len >> 1;
    const int*   lab = labels + b * SS;
    const float* lg  = logits + (size_t)b * SS * KK;

    if (w == 2) {
        float num = 0.f;
        for (int t = lane; t < len; t += 32) {
            int lt = lab[t];
            float e = lg[t * KK + lt];
            num += (t == 0) ? (start_t[lt] + e)
                            : (e + trans[lab[t - 1] * KK + lt]);
        }
#pragma unroll
        for (int o = 16; o; o >>= 1) num += __shfl_xor_sync(FULLMASK, num, o);
        if (lane == 0) {
            s_num = num;
            s_end = end_t[lab[len - 1]];
        }
    } else if (w == 0) {
        // forward: column jj of exp(trans)/21, packed in 12 f32x2 pairs
        float tE[24];
#pragma unroll
        for (int i = 0; i < KK; i++)
            tE[i] = __expf(trans[i * KK + jj]) * (1.f / 21.f);
        tE[21] = tE[22] = tE[23] = 0.f;
        ull tE2[12];
#pragma unroll
        for (int i = 0; i < 12; i++) tE2[i] = packf2(tE[2 * i], tE[2 * i + 1]);

        float a0 = (lane < KK) ? (start_t[lane] + lg[lane]) : -1e30f;
        float m0 = a0;
#pragma unroll
        for (int o = 16; o; o >>= 1)
            m0 = fmaxf(m0, __shfl_xor_sync(FULLMASK, m0, o));
        float u = __expf(a0 - m0);
        float logC = m0;
        u = crf_run_s(u, logC, tE2, s_st[0], lg, jj, 1, +1, m, lane);
        s_uf[lane] = u;
        if (lane == 0) s_cf = logC;
    } else {
        // backward: row jj of exp(trans)/21
        float tEb[24];
#pragma unroll
        for (int i = 0; i < KK; i++)
            tEb[i] = __expf(trans[jj * KK + i]) * (1.f / 21.f);
        tEb[21] = tEb[22] = tEb[23] = 0.f;
        ull tE2[12];
#pragma unroll
        for (int i = 0; i < 12; i++) tE2[i] = packf2(tEb[2 * i], tEb[2 * i + 1]);

        float v = __expf(end_t[jj]);
        float logC = 0.f;
        v = crf_run_s(v, logC, tE2, s_st[1], lg, jj, len - 1, -1,
                      len - 1 - m, lane);
        s_ub[lane] = v;
        if (lane == 0) s_cb = logC;
    }

    __syncthreads();

    if (w == 0) {
        float p = (lane < KK) ? s_uf[lane] * s_ub[lane] : 0.f;
#pragma unroll
        for (int o = 16; o; o >>= 1) p += __shfl_xor_sync(FULLMASK, p, o);
        float logZ = __logf(p) + s_cf + s_cb;
        if (lane == 0) {
            g_partial[b] = logZ - (s_num + s_end);
            __threadfence();
            int old = atomicAdd(&g_ctr, 1);
            if (old == BB - 1) {
                __threadfence();
                float tot = 0.f;
                for (int i = 0; i < BB; i++) tot += g_partial[i];
                out_nll[0] = tot;
                g_ctr = 0;
            }
        }
    }
}

// ---------------------------------------------------------------------------
extern "C" void kernel_launch(void* const* d_in, const int* in_sizes, int n_in,
                              void* d_out, int out_size) {
    const float* hidden  = (const float*)d_in[0];
    const float* W       = (const float*)d_in[1];
    const float* b       = (const float*)d_in[2];
    const float* start_t = (const float*)d_in[3];
    const float* trans   = (const float*)d_in[4];
    const float* end_t   = (const float*)d_in[5];
    const int*   labels  = (const int*)d_in[6];
    const void*  mask    = (const void*)d_in[7];

    float* out     = (float*)d_out;
    float* out_nll = out + (out_size - 1);

    cudaFuncSetAttribute(gemm_kernel,
                         cudaFuncAttributeMaxDynamicSharedMemorySize, GSMEM);

    gemm_kernel<<<1 + (BB * SS) / GR, GT, GSMEM>>>(hidden, W, b, out);
    crf_kernel<<<BB, 96>>>(out, labels, mask, start_t, trans, end_t, out_nll);
}